// round 6
// baseline (speedup 1.0000x reference)
#include <cuda_runtime.h>
#include <cstdint>
#include <math_constants.h>

// Problem constants
#define BB 4
#define SS 2048
#define EE 1024
#define HH 16
#define DD 64
#define MROWS (BB * SS)      // 8192
#define QKVN  (3 * HH * DD)  // 3072

// Scratch (allocation-free rule: __device__ globals)
__device__ float g_qkv[(size_t)MROWS * QKVN]; // 96 MB (tf32-rounded values)
__device__ float g_z[(size_t)MROWS * EE];     // 32 MB (scrambled z, tf32-rounded)
__device__ float g_xr[(size_t)MROWS * EE];    // 32 MB (tf32-rounded x)
__device__ float g_wqkv[(size_t)EE * QKVN];   // 12 MB (tf32-rounded W_qkv)
__device__ float g_wout[(size_t)EE * EE];     //  4 MB (tf32-rounded W_out)

__device__ __forceinline__ uint32_t f2tf32(float x) {
    uint32_t r;
    asm("cvt.rna.tf32.f32 %0, %1;" : "=r"(r) : "f"(x));
    return r;
}
__device__ __forceinline__ float ex2(float x) {
    float y;
    asm("ex2.approx.f32 %0, %1;" : "=f"(y) : "f"(x));
    return y;
}
__device__ __forceinline__ void cp16(void* dst, const void* src) {
    uint32_t d = (uint32_t)__cvta_generic_to_shared(dst);
    asm volatile("cp.async.cg.shared.global [%0], [%1], 16;" :: "r"(d), "l"(src));
}
#define CP_COMMIT() asm volatile("cp.async.commit_group;")
#define CP_WAIT0()  asm volatile("cp.async.wait_group 0;")

__device__ __forceinline__ void mma_tf32(float d[4], const uint32_t a[4],
                                         const uint32_t b[2]) {
    asm volatile(
        "mma.sync.aligned.m16n8k8.row.col.f32.tf32.tf32.f32 "
        "{%0,%1,%2,%3}, {%4,%5,%6,%7}, {%8,%9}, {%0,%1,%2,%3};\n"
        : "+f"(d[0]), "+f"(d[1]), "+f"(d[2]), "+f"(d[3])
        : "r"(a[0]), "r"(a[1]), "r"(a[2]), "r"(a[3]), "r"(b[0]), "r"(b[1]));
}
#define F2U __float_as_uint

// ---------------------------------------------------------------------------
// Pre-round fp32 -> tf32-valued fp32
// ---------------------------------------------------------------------------
__global__ void round_tf32_kernel(const float4* __restrict__ src,
                                  float4* __restrict__ dst, int n4) {
    int i = blockIdx.x * blockDim.x + threadIdx.x;
    if (i < n4) {
        float4 v = src[i];
        float4 o;
        o.x = __uint_as_float(f2tf32(v.x));
        o.y = __uint_as_float(f2tf32(v.y));
        o.z = __uint_as_float(f2tf32(v.z));
        o.w = __uint_as_float(f2tf32(v.w));
        dst[i] = o;
    }
}

// ---------------------------------------------------------------------------
// tf32 tensor-core GEMM, inputs pre-rounded. cp.async double-buffered.
// BM=128, BN=128, BK=32, 256 threads (8 warps 4x2), warp tile 32x64.
// Dynamic SMEM: As[2][128][36] + Bs[2][32][136] = 71680 B.
// ---------------------------------------------------------------------------
__global__ __launch_bounds__(256, 2) void tgemm_kernel(
    const float* __restrict__ A, const float* __restrict__ Bm,
    float* __restrict__ C, int M, int N, int K, int round_out)
{
    extern __shared__ float sm_g[];
    typedef float AsT[128][36];
    typedef float BsT[32][136];
    AsT* As = (AsT*)sm_g;                       // 2 stages
    BsT* Bs = (BsT*)(sm_g + 2 * 128 * 36);

    const int tid = threadIdx.x;
    const int lane = tid & 31;
    const int wid = tid >> 5;
    const int wm = wid & 3;
    const int wn = wid >> 2;
    const int r = lane >> 2;
    const int cq = lane & 3;
    const int m0 = blockIdx.y * 128;
    const int n0 = blockIdx.x * 128;

    float acc[2][8][4];
#pragma unroll
    for (int i = 0; i < 2; i++)
#pragma unroll
        for (int j = 0; j < 8; j++)
#pragma unroll
            for (int q = 0; q < 4; q++) acc[i][j][q] = 0.f;

    auto load_tile = [&](int buf, int k0) {
#pragma unroll
        for (int i = 0; i < 4; i++) {           // A: 128x32 = 1024 chunks
            int f = i * 256 + tid;
            int m = f >> 3;
            int kq = (f & 7) * 4;
            cp16(&As[buf][m][kq], A + (size_t)(m0 + m) * K + k0 + kq);
        }
#pragma unroll
        for (int i = 0; i < 4; i++) {           // B: 32x128 = 1024 chunks
            int f = i * 256 + tid;
            int kk = f >> 5;
            int nq = (f & 31) * 4;
            cp16(&Bs[buf][kk][nq], Bm + (size_t)(k0 + kk) * N + n0 + nq);
        }
        CP_COMMIT();
    };

    const int ntiles = K / 32;
    load_tile(0, 0);

    for (int it = 0; it < ntiles; it++) {
        const int cur = it & 1;
        CP_WAIT0();
        __syncthreads();
        if (it + 1 < ntiles) load_tile(cur ^ 1, (it + 1) * 32);

#pragma unroll
        for (int ks = 0; ks < 4; ks++) {
            uint32_t af[2][4];
#pragma unroll
            for (int im = 0; im < 2; im++) {
                int mr = wm * 32 + im * 16 + r;
                af[im][0] = F2U(As[cur][mr][ks * 8 + cq]);
                af[im][1] = F2U(As[cur][mr + 8][ks * 8 + cq]);
                af[im][2] = F2U(As[cur][mr][ks * 8 + cq + 4]);
                af[im][3] = F2U(As[cur][mr + 8][ks * 8 + cq + 4]);
            }
            uint32_t bf[8][2];
#pragma unroll
            for (int in_ = 0; in_ < 8; in_++) {
                int nc = wn * 64 + in_ * 8 + r;
                bf[in_][0] = F2U(Bs[cur][ks * 8 + cq][nc]);
                bf[in_][1] = F2U(Bs[cur][ks * 8 + cq + 4][nc]);
            }
#pragma unroll
            for (int im = 0; im < 2; im++)
#pragma unroll
                for (int in_ = 0; in_ < 8; in_++)
                    mma_tf32(acc[im][in_], af[im], bf[in_]);
        }
    }

    // Epilogue (optionally tf32-round outputs for the next tensor stage)
#pragma unroll
    for (int im = 0; im < 2; im++) {
#pragma unroll
        for (int in_ = 0; in_ < 8; in_++) {
            int row = m0 + wm * 32 + im * 16 + r;
            int col = n0 + wn * 64 + in_ * 8 + 2 * cq;
            float4 v;
            v.x = acc[im][in_][0]; v.y = acc[im][in_][1];
            v.z = acc[im][in_][2]; v.w = acc[im][in_][3];
            if (round_out) {
                v.x = __uint_as_float(f2tf32(v.x));
                v.y = __uint_as_float(f2tf32(v.y));
                v.z = __uint_as_float(f2tf32(v.z));
                v.w = __uint_as_float(f2tf32(v.w));
            }
            *(float2*)(C + (size_t)row * N + col) = make_float2(v.x, v.y);
            *(float2*)(C + (size_t)(row + 8) * N + col) = make_float2(v.z, v.w);
        }
    }
}

// ---------------------------------------------------------------------------
// Flash attention, tf32 MMA, base-2 softmax, cp.async double-buffered K/V.
// grid = (B*H, S/128), 256 threads (8 warps), warp = 16 query rows.
// Dynamic SMEM: Ks[2][64][68] + Vs[2][64][72] = 71680 B.
// Writes z tf32-rounded in scrambled layout: z[b, h*128+s/16, (s%16)*64+d]
// ---------------------------------------------------------------------------
__global__ __launch_bounds__(256, 2) void attn_kernel(
    const float* __restrict__ qkv, float* __restrict__ z)
{
    extern __shared__ float sm_a[];
    typedef float KsT[64][68];
    typedef float VsT[64][72];
    KsT* Ks = (KsT*)sm_a;
    VsT* Vs = (VsT*)(sm_a + 2 * 64 * 68);

    const int bh = blockIdx.x;
    const int b = bh >> 4;
    const int h = bh & 15;
    const int s0 = blockIdx.y * 128;
    const int tid = threadIdx.x;
    const int lane = tid & 31;
    const int warp = tid >> 5;
    const int r = lane >> 2;
    const int cq = lane & 3;

    const float* base = qkv + (size_t)b * SS * QKVN + h * DD;

    // Q fragments scaled by (1/8)*log2(e) so softmax runs in base-2 domain.
    const float QSCALE = 0.125f * 1.44269504088896340736f;
    uint32_t qa[8][4];
    {
        const int row0 = s0 + warp * 16 + r;
        const float* q0 = base + (size_t)row0 * QKVN;
        const float* q1 = base + (size_t)(row0 + 8) * QKVN;
#pragma unroll
        for (int kf = 0; kf < 8; kf++) {
            qa[kf][0] = f2tf32(QSCALE * q0[kf * 8 + cq]);
            qa[kf][1] = f2tf32(QSCALE * q1[kf * 8 + cq]);
            qa[kf][2] = f2tf32(QSCALE * q0[kf * 8 + cq + 4]);
            qa[kf][3] = f2tf32(QSCALE * q1[kf * 8 + cq + 4]);
        }
    }

    auto load_kv = [&](int buf, int kt) {
#pragma unroll
        for (int i = 0; i < 4; i++) {
            int f = i * 256 + tid;
            int t = f >> 4;
            int c4 = (f & 15) * 4;
            const float* row = base + (size_t)(kt + t) * QKVN + c4;
            cp16(&Ks[buf][t][c4], row + 1024);
            cp16(&Vs[buf][t][c4], row + 2048);
        }
        CP_COMMIT();
    };

    float o[8][4];
#pragma unroll
    for (int nt = 0; nt < 8; nt++)
#pragma unroll
        for (int q = 0; q < 4; q++) o[nt][q] = 0.f;
    float mrow0 = -1e30f, mrow1 = -1e30f;
    float lrow0 = 0.f, lrow1 = 0.f;

    load_kv(0, 0);

    for (int it = 0; it < SS / 64; it++) {
        const int cur = it & 1;
        CP_WAIT0();
        __syncthreads();
        if (it + 1 < SS / 64) load_kv(cur ^ 1, (it + 1) * 64);

        // S = Q @ K^T (warp: 16 x 64), scores already in log2 domain
        float s[8][4];
#pragma unroll
        for (int nt = 0; nt < 8; nt++)
#pragma unroll
            for (int q = 0; q < 4; q++) s[nt][q] = 0.f;
#pragma unroll
        for (int kf = 0; kf < 8; kf++) {
#pragma unroll
            for (int nt = 0; nt < 8; nt++) {
                uint32_t bf[2];
                bf[0] = F2U(Ks[cur][nt * 8 + r][kf * 8 + cq]);
                bf[1] = F2U(Ks[cur][nt * 8 + r][kf * 8 + cq + 4]);
                mma_tf32(s[nt], qa[kf], bf);
            }
        }

        // Online softmax (base 2)
        float mt0 = -1e30f, mt1 = -1e30f;
#pragma unroll
        for (int nt = 0; nt < 8; nt++) {
            mt0 = fmaxf(mt0, fmaxf(s[nt][0], s[nt][1]));
            mt1 = fmaxf(mt1, fmaxf(s[nt][2], s[nt][3]));
        }
        mt0 = fmaxf(mt0, __shfl_xor_sync(0xffffffffu, mt0, 1));
        mt0 = fmaxf(mt0, __shfl_xor_sync(0xffffffffu, mt0, 2));
        mt1 = fmaxf(mt1, __shfl_xor_sync(0xffffffffu, mt1, 1));
        mt1 = fmaxf(mt1, __shfl_xor_sync(0xffffffffu, mt1, 2));
        float mn0 = fmaxf(mrow0, mt0);
        float mn1 = fmaxf(mrow1, mt1);
        float corr0 = ex2(mrow0 - mn0);
        float corr1 = ex2(mrow1 - mn1);
        float ls0 = 0.f, ls1 = 0.f;
#pragma unroll
        for (int nt = 0; nt < 8; nt++) {
            float p0 = ex2(s[nt][0] - mn0);
            float p1 = ex2(s[nt][1] - mn0);
            float p2 = ex2(s[nt][2] - mn1);
            float p3 = ex2(s[nt][3] - mn1);
            ls0 += p0 + p1;
            ls1 += p2 + p3;
            // reuse s[] as tf32-rounded P (bit pattern in float regs)
            s[nt][0] = __uint_as_float(f2tf32(p0));
            s[nt][1] = __uint_as_float(f2tf32(p1));
            s[nt][2] = __uint_as_float(f2tf32(p2));
            s[nt][3] = __uint_as_float(f2tf32(p3));
        }
        ls0 += __shfl_xor_sync(0xffffffffu, ls0, 1);
        ls0 += __shfl_xor_sync(0xffffffffu, ls0, 2);
        ls1 += __shfl_xor_sync(0xffffffffu, ls1, 1);
        ls1 += __shfl_xor_sync(0xffffffffu, ls1, 2);
        lrow0 = lrow0 * corr0 + ls0;
        lrow1 = lrow1 * corr1 + ls1;
        mrow0 = mn0;
        mrow1 = mn1;
#pragma unroll
        for (int nt = 0; nt < 8; nt++) {
            o[nt][0] *= corr0;
            o[nt][1] *= corr0;
            o[nt][2] *= corr1;
            o[nt][3] *= corr1;
        }

        // O += P @ V. Relayout P (C-frag) -> A-frag via intra-quad shuffles.
        const int src1 = (lane & ~3) | (cq >> 1);
        const int src2 = src1 + 2;
        const bool oddc = (cq & 1);
#pragma unroll
        for (int ks = 0; ks < 8; ks++) {
            uint32_t pa[4];
            {
                float v0 = __shfl_sync(0xffffffffu, s[ks][0], src1);
                float v1 = __shfl_sync(0xffffffffu, s[ks][1], src1);
                pa[0] = F2U(oddc ? v1 : v0);
                float w0 = __shfl_sync(0xffffffffu, s[ks][0], src2);
                float w1 = __shfl_sync(0xffffffffu, s[ks][1], src2);
                pa[2] = F2U(oddc ? w1 : w0);
                float x0 = __shfl_sync(0xffffffffu, s[ks][2], src1);
                float x1 = __shfl_sync(0xffffffffu, s[ks][3], src1);
                pa[1] = F2U(oddc ? x1 : x0);
                float y0 = __shfl_sync(0xffffffffu, s[ks][2], src2);
                float y1 = __shfl_sync(0xffffffffu, s[ks][3], src2);
                pa[3] = F2U(oddc ? y1 : y0);
            }
#pragma unroll
            for (int nt = 0; nt < 8; nt++) {
                uint32_t bf[2];
                bf[0] = F2U(Vs[cur][ks * 8 + cq][nt * 8 + r]);
                bf[1] = F2U(Vs[cur][ks * 8 + cq + 4][nt * 8 + r]);
                mma_tf32(o[nt], pa, bf);
            }
        }
    }

    // Epilogue: normalize, tf32-round, write scrambled layout
    float inv0 = 1.f / lrow0;
    float inv1 = 1.f / lrow1;
    int sg0 = s0 + warp * 16 + r;
    int sg1 = sg0 + 8;
    int zr0 = h * 128 + (sg0 >> 4);
    int zr1 = h * 128 + (sg1 >> 4);
    float* d0 = z + ((size_t)b * SS + zr0) * EE + (sg0 & 15) * 64;
    float* d1 = z + ((size_t)b * SS + zr1) * EE + (sg1 & 15) * 64;
#pragma unroll
    for (int nt = 0; nt < 8; nt++) {
        int col = nt * 8 + 2 * cq;
        float2 a0, a1;
        a0.x = __uint_as_float(f2tf32(o[nt][0] * inv0));
        a0.y = __uint_as_float(f2tf32(o[nt][1] * inv0));
        a1.x = __uint_as_float(f2tf32(o[nt][2] * inv1));
        a1.y = __uint_as_float(f2tf32(o[nt][3] * inv1));
        *(float2*)(d0 + col) = a0;
        *(float2*)(d1 + col) = a1;
    }
}

// ---------------------------------------------------------------------------
extern "C" void kernel_launch(void* const* d_in, const int* in_sizes, int n_in,
                              void* d_out, int out_size)
{
    (void)in_sizes; (void)n_in; (void)out_size;
    const float* x    = (const float*)d_in[0];
    const float* Wqkv = (const float*)d_in[1];
    const float* Wout = (const float*)d_in[2];
    float* out = (float*)d_out;

    void *p_qkv, *p_z, *p_xr, *p_wq, *p_wo;
    cudaGetSymbolAddress(&p_qkv, g_qkv);
    cudaGetSymbolAddress(&p_z, g_z);
    cudaGetSymbolAddress(&p_xr, g_xr);
    cudaGetSymbolAddress(&p_wq, g_wqkv);
    cudaGetSymbolAddress(&p_wo, g_wout);
    float* qkv = (float*)p_qkv;
    float* zb  = (float*)p_z;
    float* xr  = (float*)p_xr;
    float* wq  = (float*)p_wq;
    float* wo  = (float*)p_wo;

    const int SMEM = 71680;
    cudaFuncSetAttribute(tgemm_kernel,
                         cudaFuncAttributeMaxDynamicSharedMemorySize, SMEM);
    cudaFuncSetAttribute(attn_kernel,
                         cudaFuncAttributeMaxDynamicSharedMemorySize, SMEM);

    dim3 blk(256);
    // 0) Pre-round inputs to tf32 values
    {
        int n4x = MROWS * EE / 4;
        int n4q = EE * QKVN / 4;
        int n4o = EE * EE / 4;
        round_tf32_kernel<<<(n4x + 255) / 256, blk>>>((const float4*)x,
                                                      (float4*)xr, n4x);
        round_tf32_kernel<<<(n4q + 255) / 256, blk>>>((const float4*)Wqkv,
                                                      (float4*)wq, n4q);
        round_tf32_kernel<<<(n4o + 255) / 256, blk>>>((const float4*)Wout,
                                                      (float4*)wo, n4o);
    }
    // 1) QKV projection (round outputs to tf32 for attention)
    tgemm_kernel<<<dim3(QKVN / 128, MROWS / 128), blk, SMEM>>>(
        xr, wq, qkv, MROWS, QKVN, EE, 1);
    // 2) Attention (writes tf32-rounded scrambled z)
    attn_kernel<<<dim3(BB * HH, SS / 128), blk, SMEM>>>(qkv, zb);
    // 3) Output projection (full fp32 output)
    tgemm_kernel<<<dim3(EE / 128, MROWS / 128), blk, SMEM>>>(
        zb, wo, out, MROWS, EE, EE, 0);
}

// round 7
// speedup vs baseline: 2.0567x; 2.0567x over previous
#include <cuda_runtime.h>
#include <cuda_fp16.h>
#include <cstdint>

// Problem constants
#define BB 4
#define SS 2048
#define EE 1024
#define HH 16
#define DD 64
#define MROWS (BB * SS)      // 8192
#define QKVN  (3 * HH * DD)  // 3072
#define PITCH 72             // SMEM row pitch in halves (144B, conflict-free)

// Scratch (allocation-free rule: __device__ globals)
__device__ __half g_qkv[(size_t)MROWS * QKVN];  // 48 MB
__device__ __half g_z[(size_t)MROWS * EE];      // 16 MB (scrambled z)
__device__ __half g_xh[(size_t)MROWS * EE];     // 16 MB (x fp16)
__device__ __half g_wqt[(size_t)QKVN * EE];     //  6 MB (W_qkv^T fp16 [N,K])
__device__ __half g_wot[(size_t)EE * EE];       //  2 MB (W_out^T fp16 [N,K])

__device__ __forceinline__ uint32_t h2pack(float lo, float hi) {
    uint32_t r;
    asm("cvt.rn.f16x2.f32 %0, %1, %2;" : "=r"(r) : "f"(hi), "f"(lo));
    return r;
}
__device__ __forceinline__ float ex2(float x) {
    float y;
    asm("ex2.approx.f32 %0, %1;" : "=f"(y) : "f"(x));
    return y;
}
__device__ __forceinline__ void cp16(void* dst, const void* src) {
    uint32_t d = (uint32_t)__cvta_generic_to_shared(dst);
    asm volatile("cp.async.cg.shared.global [%0], [%1], 16;" :: "r"(d), "l"(src));
}
#define CP_COMMIT() asm volatile("cp.async.commit_group;")
#define CP_WAIT0()  asm volatile("cp.async.wait_group 0;")

__device__ __forceinline__ void ldsm4(uint32_t r[4], uint32_t addr) {
    asm volatile("ldmatrix.sync.aligned.m8n8.x4.shared.b16 {%0,%1,%2,%3}, [%4];"
                 : "=r"(r[0]), "=r"(r[1]), "=r"(r[2]), "=r"(r[3]) : "r"(addr));
}
__device__ __forceinline__ void ldsm4t(uint32_t r[4], uint32_t addr) {
    asm volatile("ldmatrix.sync.aligned.m8n8.x4.trans.shared.b16 {%0,%1,%2,%3}, [%4];"
                 : "=r"(r[0]), "=r"(r[1]), "=r"(r[2]), "=r"(r[3]) : "r"(addr));
}
__device__ __forceinline__ void mma16816(float d[4], const uint32_t a[4],
                                         uint32_t b0, uint32_t b1) {
    asm volatile(
        "mma.sync.aligned.m16n8k16.row.col.f32.f16.f16.f32 "
        "{%0,%1,%2,%3}, {%4,%5,%6,%7}, {%8,%9}, {%0,%1,%2,%3};\n"
        : "+f"(d[0]), "+f"(d[1]), "+f"(d[2]), "+f"(d[3])
        : "r"(a[0]), "r"(a[1]), "r"(a[2]), "r"(a[3]), "r"(b0), "r"(b1));
}
__device__ __forceinline__ uint32_t sptr(const void* p) {
    return (uint32_t)__cvta_generic_to_shared(p);
}

// ---------------------------------------------------------------------------
// Pre-pass: fp32 -> fp16 copy (x) and fp32 -> fp16 transpose (weights)
// ---------------------------------------------------------------------------
__global__ void cvt_half_kernel(const float4* __restrict__ src,
                                uint2* __restrict__ dst, int n4) {
    int i = blockIdx.x * blockDim.x + threadIdx.x;
    if (i < n4) {
        float4 v = src[i];
        uint2 o;
        o.x = h2pack(v.x, v.y);
        o.y = h2pack(v.z, v.w);
        dst[i] = o;
    }
}
// src [R][C] fp32 -> dst [C][R] fp16
__global__ void cvtT_kernel(const float* __restrict__ src,
                            __half* __restrict__ dst, int R, int C) {
    __shared__ float t[32][33];
    int bx = blockIdx.x, by = blockIdx.y;
    int tx = threadIdx.x, ty = threadIdx.y;
    int x = bx * 32 + tx;
#pragma unroll
    for (int i = 0; i < 4; i++) {
        int y = by * 32 + ty + i * 8;
        t[ty + i * 8][tx] = src[(size_t)y * C + x];
    }
    __syncthreads();
    int xo = by * 32 + tx;
#pragma unroll
    for (int i = 0; i < 4; i++) {
        int yo = bx * 32 + ty + i * 8;
        dst[(size_t)yo * R + xo] = __float2half_rn(t[tx][ty + i * 8]);
    }
}

// ---------------------------------------------------------------------------
// fp16 tensor-core GEMM: C[M,N] = A[M,K] @ Bt[N,K]^T.
// BM=128, BN=128, BK=64, 256 threads (8 warps 4x2), warp tile 32x64.
// A,Bt fp16; C fp16 (half_out=1) or fp32. ldmatrix fragment loads.
// Dynamic SMEM: 2 stages x (As[128][72] + Bs[128][72]) halves = 73728 B.
// ---------------------------------------------------------------------------
__global__ __launch_bounds__(256, 2) void hgemm_kernel(
    const __half* __restrict__ A, const __half* __restrict__ Bt,
    void* __restrict__ Cv, int M, int N, int K, int half_out)
{
    extern __shared__ __half smh[];
    const int stA = 128 * PITCH;           // halves per A stage
    __half* Asm = smh;                     // [2][128][PITCH]
    __half* Bsm = smh + 2 * stA;           // [2][128][PITCH]

    const int tid = threadIdx.x;
    const int lane = tid & 31;
    const int wid = tid >> 5;
    const int wm = wid & 3;
    const int wn = wid >> 2;
    const int r = lane >> 2;
    const int cq = lane & 3;
    const int m0 = blockIdx.y * 128;
    const int n0 = blockIdx.x * 128;

    // ldmatrix per-lane offsets
    const int a_row_l = ((lane >> 3) & 1) * 8 + (lane & 7);
    const int a_col_l = ((lane >> 4) & 1) * 8;
    const int b_row_l = lane & 7;
    const int b_col_l = (lane >> 3) * 8;

    float acc[2][8][4];
#pragma unroll
    for (int i = 0; i < 2; i++)
#pragma unroll
        for (int j = 0; j < 8; j++)
#pragma unroll
            for (int q = 0; q < 4; q++) acc[i][j][q] = 0.f;

    auto load_tile = [&](int buf, int k0) {
#pragma unroll
        for (int i = 0; i < 4; i++) {       // A: 128 rows x 8 chunks
            int f = i * 256 + tid;
            int row = f >> 3;
            int c = (f & 7) * 8;
            cp16(Asm + buf * stA + row * PITCH + c,
                 A + (size_t)(m0 + row) * K + k0 + c);
        }
#pragma unroll
        for (int i = 0; i < 4; i++) {       // B: 128 rows x 8 chunks
            int f = i * 256 + tid;
            int row = f >> 3;
            int c = (f & 7) * 8;
            cp16(Bsm + buf * stA + row * PITCH + c,
                 Bt + (size_t)(n0 + row) * K + k0 + c);
        }
        CP_COMMIT();
    };

    const int ntiles = K / 64;
    load_tile(0, 0);

    for (int it = 0; it < ntiles; it++) {
        const int cur = it & 1;
        CP_WAIT0();
        __syncthreads();
        if (it + 1 < ntiles) load_tile(cur ^ 1, (it + 1) * 64);

#pragma unroll
        for (int ksp = 0; ksp < 2; ksp++) {
            uint32_t af[2][2][4];
#pragma unroll
            for (int im = 0; im < 2; im++)
#pragma unroll
                for (int sub = 0; sub < 2; sub++) {
                    int ks = ksp * 2 + sub;
                    uint32_t ad = sptr(Asm + cur * stA +
                                       (wm * 32 + im * 16 + a_row_l) * PITCH +
                                       ks * 16 + a_col_l);
                    ldsm4(af[im][sub], ad);
                }
#pragma unroll
            for (int nt = 0; nt < 8; nt++) {
                uint32_t bf[4];
                uint32_t bd = sptr(Bsm + cur * stA +
                                   (wn * 64 + nt * 8 + b_row_l) * PITCH +
                                   ksp * 32 + b_col_l);
                ldsm4(bf, bd);
#pragma unroll
                for (int im = 0; im < 2; im++) {
                    mma16816(acc[im][nt], af[im][0], bf[0], bf[1]);
                    mma16816(acc[im][nt], af[im][1], bf[2], bf[3]);
                }
            }
        }
    }

    // Epilogue
    if (half_out) {
        __half* C = (__half*)Cv;
#pragma unroll
        for (int im = 0; im < 2; im++)
#pragma unroll
            for (int nt = 0; nt < 8; nt++) {
                int row = m0 + wm * 32 + im * 16 + r;
                int col = n0 + wn * 64 + nt * 8 + 2 * cq;
                *(uint32_t*)(C + (size_t)row * N + col) =
                    h2pack(acc[im][nt][0], acc[im][nt][1]);
                *(uint32_t*)(C + (size_t)(row + 8) * N + col) =
                    h2pack(acc[im][nt][2], acc[im][nt][3]);
            }
    } else {
        float* C = (float*)Cv;
#pragma unroll
        for (int im = 0; im < 2; im++)
#pragma unroll
            for (int nt = 0; nt < 8; nt++) {
                int row = m0 + wm * 32 + im * 16 + r;
                int col = n0 + wn * 64 + nt * 8 + 2 * cq;
                *(float2*)(C + (size_t)row * N + col) =
                    make_float2(acc[im][nt][0], acc[im][nt][1]);
                *(float2*)(C + (size_t)(row + 8) * N + col) =
                    make_float2(acc[im][nt][2], acc[im][nt][3]);
            }
    }
}

// ---------------------------------------------------------------------------
// Flash attention, fp16 MMA m16n8k16, base-2 softmax, cp.async 2-stage.
// grid = (B*H, S/128), 256 threads (8 warps), warp = 16 query rows.
// Dynamic SMEM: Ks[2][64][72] + Vs[2][64][72] halves = 36864 B.
// Writes z fp16 in scrambled layout: z[b, h*128+s/16, (s%16)*64+d]
// ---------------------------------------------------------------------------
__global__ __launch_bounds__(256, 2) void attn_kernel(
    const __half* __restrict__ qkv, __half* __restrict__ z)
{
    extern __shared__ __half sma[];
    const int stK = 64 * PITCH;
    __half* Ksm = sma;                 // [2][64][PITCH]
    __half* Vsm = sma + 2 * stK;       // [2][64][PITCH]

    const int bh = blockIdx.x;
    const int b = bh >> 4;
    const int h = bh & 15;
    const int s0 = blockIdx.y * 128;
    const int tid = threadIdx.x;
    const int lane = tid & 31;
    const int warp = tid >> 5;
    const int r = lane >> 2;
    const int cq = lane & 3;

    // ldmatrix per-lane offsets
    const int k_row_l = ((lane >> 4) & 1) * 8 + (lane & 7);
    const int k_col_l = ((lane >> 3) & 1) * 8;
    const int v_row_l = ((lane >> 3) & 1) * 8 + (lane & 7);
    const int v_col_l = ((lane >> 4) & 1) * 8;

    const __half* base = qkv + (size_t)b * SS * QKVN + h * DD;

    // Q fragments scaled by (1/8)*log2(e), packed fp16
    const float QSCALE = 0.125f * 1.44269504088896340736f;
    uint32_t qa[4][4];
    {
        const int row0 = s0 + warp * 16 + r;
        const __half* q0 = base + (size_t)row0 * QKVN;
        const __half* q1 = base + (size_t)(row0 + 8) * QKVN;
#pragma unroll
        for (int ks = 0; ks < 4; ks++) {
            float2 f0 = __half22float2(*(const __half2*)(q0 + 16 * ks + 2 * cq));
            float2 f1 = __half22float2(*(const __half2*)(q1 + 16 * ks + 2 * cq));
            float2 f2 = __half22float2(*(const __half2*)(q0 + 16 * ks + 8 + 2 * cq));
            float2 f3 = __half22float2(*(const __half2*)(q1 + 16 * ks + 8 + 2 * cq));
            qa[ks][0] = h2pack(f0.x * QSCALE, f0.y * QSCALE);
            qa[ks][1] = h2pack(f1.x * QSCALE, f1.y * QSCALE);
            qa[ks][2] = h2pack(f2.x * QSCALE, f2.y * QSCALE);
            qa[ks][3] = h2pack(f3.x * QSCALE, f3.y * QSCALE);
        }
    }

    auto load_kv = [&](int buf, int kt) {
#pragma unroll
        for (int i = 0; i < 4; i++) {
            int f = i * 256 + tid;          // 0..1023
            int isv = f >> 9;               // 0: K, 1: V
            int g = f & 511;
            int t = g >> 3;
            int c = (g & 7) * 8;
            const __half* src = base + (size_t)(kt + t) * QKVN +
                                (isv ? 2048 : 1024) + c;
            __half* dst = (isv ? Vsm : Ksm) + buf * stK + t * PITCH + c;
            cp16(dst, src);
        }
        CP_COMMIT();
    };

    float o[8][4];
#pragma unroll
    for (int nt = 0; nt < 8; nt++)
#pragma unroll
        for (int q = 0; q < 4; q++) o[nt][q] = 0.f;
    float mrow0 = -1e30f, mrow1 = -1e30f;
    float lrow0 = 0.f, lrow1 = 0.f;

    load_kv(0, 0);

    for (int it = 0; it < SS / 64; it++) {
        const int cur = it & 1;
        CP_WAIT0();
        __syncthreads();
        if (it + 1 < SS / 64) load_kv(cur ^ 1, (it + 1) * 64);

        // S = Q @ K^T (warp: 16 x 64), scores in log2 domain
        float s[8][4];
#pragma unroll
        for (int nt = 0; nt < 8; nt++)
#pragma unroll
            for (int q = 0; q < 4; q++) s[nt][q] = 0.f;
#pragma unroll
        for (int ks = 0; ks < 4; ks++) {
#pragma unroll
            for (int ntp = 0; ntp < 4; ntp++) {
                uint32_t kb[4];
                uint32_t kd = sptr(Ksm + cur * stK +
                                   (ntp * 16 + k_row_l) * PITCH +
                                   ks * 16 + k_col_l);
                ldsm4(kb, kd);
                mma16816(s[2 * ntp],     qa[ks], kb[0], kb[1]);
                mma16816(s[2 * ntp + 1], qa[ks], kb[2], kb[3]);
            }
        }

        // Online softmax (base 2)
        float mt0 = -1e30f, mt1 = -1e30f;
#pragma unroll
        for (int nt = 0; nt < 8; nt++) {
            mt0 = fmaxf(mt0, fmaxf(s[nt][0], s[nt][1]));
            mt1 = fmaxf(mt1, fmaxf(s[nt][2], s[nt][3]));
        }
        mt0 = fmaxf(mt0, __shfl_xor_sync(0xffffffffu, mt0, 1));
        mt0 = fmaxf(mt0, __shfl_xor_sync(0xffffffffu, mt0, 2));
        mt1 = fmaxf(mt1, __shfl_xor_sync(0xffffffffu, mt1, 1));
        mt1 = fmaxf(mt1, __shfl_xor_sync(0xffffffffu, mt1, 2));
        float mn0 = fmaxf(mrow0, mt0);
        float mn1 = fmaxf(mrow1, mt1);
        float corr0 = ex2(mrow0 - mn0);
        float corr1 = ex2(mrow1 - mn1);
        float ls0 = 0.f, ls1 = 0.f;
#pragma unroll
        for (int nt = 0; nt < 8; nt++) {
            s[nt][0] = ex2(s[nt][0] - mn0);
            s[nt][1] = ex2(s[nt][1] - mn0);
            s[nt][2] = ex2(s[nt][2] - mn1);
            s[nt][3] = ex2(s[nt][3] - mn1);
            ls0 += s[nt][0] + s[nt][1];
            ls1 += s[nt][2] + s[nt][3];
        }
        ls0 += __shfl_xor_sync(0xffffffffu, ls0, 1);
        ls0 += __shfl_xor_sync(0xffffffffu, ls0, 2);
        ls1 += __shfl_xor_sync(0xffffffffu, ls1, 1);
        ls1 += __shfl_xor_sync(0xffffffffu, ls1, 2);
        lrow0 = lrow0 * corr0 + ls0;
        lrow1 = lrow1 * corr1 + ls1;
        mrow0 = mn0;
        mrow1 = mn1;
#pragma unroll
        for (int nt = 0; nt < 8; nt++) {
            o[nt][0] *= corr0;
            o[nt][1] *= corr0;
            o[nt][2] *= corr1;
            o[nt][3] *= corr1;
        }

        // Pack P: S C-frag layout == P A-frag layout for fp16 (no shuffles)
        uint32_t pa[4][4];
#pragma unroll
        for (int ks = 0; ks < 4; ks++) {
            pa[ks][0] = h2pack(s[2 * ks][0], s[2 * ks][1]);
            pa[ks][1] = h2pack(s[2 * ks][2], s[2 * ks][3]);
            pa[ks][2] = h2pack(s[2 * ks + 1][0], s[2 * ks + 1][1]);
            pa[ks][3] = h2pack(s[2 * ks + 1][2], s[2 * ks + 1][3]);
        }

        // O += P @ V  (V fragments via ldmatrix.trans)
#pragma unroll
        for (int ks = 0; ks < 4; ks++) {
#pragma unroll
            for (int dp = 0; dp < 4; dp++) {
                uint32_t vb[4];
                uint32_t vd = sptr(Vsm + cur * stK +
                                   (ks * 16 + v_row_l) * PITCH +
                                   dp * 16 + v_col_l);
                ldsm4t(vb, vd);
                mma16816(o[2 * dp],     pa[ks], vb[0], vb[1]);
                mma16816(o[2 * dp + 1], pa[ks], vb[2], vb[3]);
            }
        }
    }

    // Epilogue: normalize, fp16, scrambled layout
    float inv0 = 1.f / lrow0;
    float inv1 = 1.f / lrow1;
    int sg0 = s0 + warp * 16 + r;
    int sg1 = sg0 + 8;
    int zr0 = h * 128 + (sg0 >> 4);
    int zr1 = h * 128 + (sg1 >> 4);
    __half* d0 = z + ((size_t)b * SS + zr0) * EE + (sg0 & 15) * 64;
    __half* d1 = z + ((size_t)b * SS + zr1) * EE + (sg1 & 15) * 64;
#pragma unroll
    for (int nt = 0; nt < 8; nt++) {
        int col = nt * 8 + 2 * cq;
        *(uint32_t*)(d0 + col) = h2pack(o[nt][0] * inv0, o[nt][1] * inv0);
        *(uint32_t*)(d1 + col) = h2pack(o[nt][2] * inv1, o[nt][3] * inv1);
    }
}

// ---------------------------------------------------------------------------
extern "C" void kernel_launch(void* const* d_in, const int* in_sizes, int n_in,
                              void* d_out, int out_size)
{
    (void)in_sizes; (void)n_in; (void)out_size;
    const float* x    = (const float*)d_in[0];
    const float* Wqkv = (const float*)d_in[1];
    const float* Wout = (const float*)d_in[2];
    float* out = (float*)d_out;

    void *p_qkv, *p_z, *p_xh, *p_wqt, *p_wot;
    cudaGetSymbolAddress(&p_qkv, g_qkv);
    cudaGetSymbolAddress(&p_z, g_z);
    cudaGetSymbolAddress(&p_xh, g_xh);
    cudaGetSymbolAddress(&p_wqt, g_wqt);
    cudaGetSymbolAddress(&p_wot, g_wot);
    __half* qkv = (__half*)p_qkv;
    __half* zb  = (__half*)p_z;
    __half* xh  = (__half*)p_xh;
    __half* wqt = (__half*)p_wqt;
    __half* wot = (__half*)p_wot;

    const int SMEM_G = 2 * 2 * 128 * PITCH * 2;  // 73728
    const int SMEM_A = 2 * 2 * 64 * PITCH * 2;   // 36864
    cudaFuncSetAttribute(hgemm_kernel,
                         cudaFuncAttributeMaxDynamicSharedMemorySize, SMEM_G);
    cudaFuncSetAttribute(attn_kernel,
                         cudaFuncAttributeMaxDynamicSharedMemorySize, SMEM_A);

    dim3 blk(256);
    // 0) Pre-pass: x -> fp16; weights -> fp16 transposed [N,K]
    {
        int n4x = MROWS * EE / 4;
        cvt_half_kernel<<<(n4x + 255) / 256, blk>>>((const float4*)x,
                                                    (uint2*)xh, n4x);
        cvtT_kernel<<<dim3(QKVN / 32, EE / 32), dim3(32, 8)>>>(Wqkv, wqt,
                                                               EE, QKVN);
        cvtT_kernel<<<dim3(EE / 32, EE / 32), dim3(32, 8)>>>(Wout, wot,
                                                             EE, EE);
    }
    // 1) QKV projection -> fp16 qkv
    hgemm_kernel<<<dim3(QKVN / 128, MROWS / 128), blk, SMEM_G>>>(
        xh, wqt, qkv, MROWS, QKVN, EE, 1);
    // 2) Attention -> fp16 scrambled z
    attn_kernel<<<dim3(BB * HH, SS / 128), blk, SMEM_A>>>(qkv, zb);
    // 3) Output projection -> fp32 out
    hgemm_kernel<<<dim3(EE / 128, MROWS / 128), blk, SMEM_G>>>(
        zb, wot, out, MROWS, EE, EE, 0);
}